// round 2
// baseline (speedup 1.0000x reference)
#include <cuda_runtime.h>
#include <cstdint>

#define N_NODES 200000
#define N_GRAPHS 4000
#define C1 32
#define H 64

// Scratch (device globals; allocation is forbidden)
__device__ __align__(16) float g_agg1[(size_t)N_NODES * C1];   // layer1 neighbor sums
__device__ __align__(16) float g_deg[N_NODES];                  // degrees
__device__ __align__(16) float g_h1[(size_t)N_NODES * H];       // layer1 output
__device__ __align__(16) float g_agg2[(size_t)N_NODES * H];     // layer2 neighbor sums
__device__ __align__(16) float g_h2[(size_t)N_NODES * H];       // layer2 output
__device__ __align__(16) float g_pool[(size_t)N_GRAPHS * H];    // pooled sums
__device__ __align__(16) float g_cnt[N_GRAPHS];                 // nodes per graph
__device__ int g_idx_is_32;                                     // 1 if indices are int32

// ---------------------------------------------------------------------------
// Probe index dtype: if interpreting the buffer as int64 yields out-of-range
// values, the underlying data is int32. (Valid int64 indices are < N_NODES,
// so their high words are zero.)
__global__ void k_probe(const void* ei, int n_elem) {
    if (threadIdx.x == 0 && blockIdx.x == 0) {
        const long long* p = (const long long*)ei;
        int cnt = n_elem < 64 ? n_elem : 64;
        int is32 = 0;
        for (int i = 0; i < cnt; i++) {
            long long v = p[i];
            if (v < 0 || v >= N_NODES) { is32 = 1; break; }
        }
        g_idx_is_32 = is32;
    }
}

__device__ __forceinline__ int load_idx(const void* base, long long i) {
    if (g_idx_is_32) return ((const int*)base)[i];
    return (int)((const long long*)base)[i];
}

// ---------------------------------------------------------------------------
__global__ void k_zero() {
    int i = blockIdx.x * blockDim.x + threadIdx.x;
    int stride = gridDim.x * blockDim.x;
    for (int j = i; j < N_NODES * C1; j += stride) g_agg1[j] = 0.f;
    for (int j = i; j < N_NODES * H;  j += stride) g_agg2[j] = 0.f;
    for (int j = i; j < N_NODES;      j += stride) g_deg[j]  = 0.f;
    for (int j = i; j < N_GRAPHS * H; j += stride) g_pool[j] = 0.f;
    for (int j = i; j < N_GRAPHS;     j += stride) g_cnt[j]  = 0.f;
}

// ---------------------------------------------------------------------------
// Layer-1 edge scatter: 8 float4 groups per edge (32 channels)
// ei holds src at [0,E) and dst at [E,2E) in whichever dtype.
__global__ void k_edge1(const float* __restrict__ x,
                        const void* __restrict__ ei, int E) {
    long long idx = (long long)blockIdx.x * blockDim.x + threadIdx.x;
    if (idx >= (long long)E * 8) return;
    long long e = idx >> 3;
    int g = (int)(idx & 7);
    int s = load_idx(ei, e);
    int d = load_idx(ei, e + E);
    float4 v = *reinterpret_cast<const float4*>(x + (size_t)s * C1 + g * 4);
    atomicAdd(reinterpret_cast<float4*>(g_agg1 + (size_t)d * C1 + g * 4), v);
    if (g == 0) atomicAdd(&g_deg[d], 1.0f);
}

// ---------------------------------------------------------------------------
// Layer-1 node update: h1 = relu(mean @ W1_l^T + b1 + x @ W1_r^T)
__global__ void k_node1(const float* __restrict__ x,
                        const float* __restrict__ Wl,
                        const float* __restrict__ b,
                        const float* __restrict__ Wr) {
    __shared__ float sWl[H * C1], sWr[H * C1], sb[H];
    for (int i = threadIdx.x; i < H * C1; i += blockDim.x) { sWl[i] = Wl[i]; sWr[i] = Wr[i]; }
    for (int i = threadIdx.x; i < H; i += blockDim.x) sb[i] = b[i];
    __syncthreads();

    int n = blockIdx.x * blockDim.x + threadIdx.x;
    if (n >= N_NODES) return;

    float inv = 1.0f / fmaxf(g_deg[n], 1.0f);
    float m[C1], xv[C1];
    const float4* ag = reinterpret_cast<const float4*>(g_agg1 + (size_t)n * C1);
    const float4* xr = reinterpret_cast<const float4*>(x + (size_t)n * C1);
#pragma unroll
    for (int k = 0; k < C1 / 4; k++) {
        float4 a = ag[k];
        m[4 * k + 0] = a.x * inv; m[4 * k + 1] = a.y * inv;
        m[4 * k + 2] = a.z * inv; m[4 * k + 3] = a.w * inv;
        float4 xb = xr[k];
        xv[4 * k + 0] = xb.x; xv[4 * k + 1] = xb.y;
        xv[4 * k + 2] = xb.z; xv[4 * k + 3] = xb.w;
    }
    for (int j = 0; j < H; j++) {
        float acc = sb[j];
#pragma unroll
        for (int k = 0; k < C1; k++)
            acc += m[k] * sWl[j * C1 + k] + xv[k] * sWr[j * C1 + k];
        g_h1[(size_t)n * H + j] = fmaxf(acc, 0.0f);
    }
}

// ---------------------------------------------------------------------------
// Layer-2 edge scatter: 16 float4 groups per edge (64 channels)
__global__ void k_edge2(const void* __restrict__ ei, int E) {
    long long idx = (long long)blockIdx.x * blockDim.x + threadIdx.x;
    if (idx >= (long long)E * 16) return;
    long long e = idx >> 4;
    int g = (int)(idx & 15);
    int s = load_idx(ei, e);
    int d = load_idx(ei, e + E);
    float4 v = *reinterpret_cast<const float4*>(g_h1 + (size_t)s * H + g * 4);
    atomicAdd(reinterpret_cast<float4*>(g_agg2 + (size_t)d * H + g * 4), v);
}

// ---------------------------------------------------------------------------
// Layer-2 node update: h2 = relu(mean @ W2_l^T + b2 + h1 @ W2_r^T)
__global__ void __launch_bounds__(128) k_node2(const float* __restrict__ Wl,
                                               const float* __restrict__ b,
                                               const float* __restrict__ Wr) {
    __shared__ float sWl[H * H], sWr[H * H], sb[H];
    for (int i = threadIdx.x; i < H * H; i += blockDim.x) { sWl[i] = Wl[i]; sWr[i] = Wr[i]; }
    for (int i = threadIdx.x; i < H; i += blockDim.x) sb[i] = b[i];
    __syncthreads();

    int n = blockIdx.x * blockDim.x + threadIdx.x;
    if (n >= N_NODES) return;

    float inv = 1.0f / fmaxf(g_deg[n], 1.0f);
    float m[H], hv[H];
    const float4* ag = reinterpret_cast<const float4*>(g_agg2 + (size_t)n * H);
    const float4* hr = reinterpret_cast<const float4*>(g_h1 + (size_t)n * H);
#pragma unroll
    for (int k = 0; k < H / 4; k++) {
        float4 a = ag[k];
        m[4 * k + 0] = a.x * inv; m[4 * k + 1] = a.y * inv;
        m[4 * k + 2] = a.z * inv; m[4 * k + 3] = a.w * inv;
        float4 hb = hr[k];
        hv[4 * k + 0] = hb.x; hv[4 * k + 1] = hb.y;
        hv[4 * k + 2] = hb.z; hv[4 * k + 3] = hb.w;
    }
    for (int j = 0; j < H; j++) {
        float accl = sb[j], accr = 0.0f;
#pragma unroll
        for (int k = 0; k < H; k++) {
            accl += m[k] * sWl[j * H + k];
            accr += hv[k] * sWr[j * H + k];
        }
        g_h2[(size_t)n * H + j] = fmaxf(accl + accr, 0.0f);
    }
}

// ---------------------------------------------------------------------------
// Graph mean-pool accumulate (+ per-graph counts)
__global__ void k_pool(const void* __restrict__ batch) {
    long long idx = (long long)blockIdx.x * blockDim.x + threadIdx.x;
    if (idx >= (long long)N_NODES * 16) return;
    long long n = idx >> 4;
    int g = (int)(idx & 15);
    int bg = load_idx(batch, n);
    float4 v = *reinterpret_cast<const float4*>(g_h2 + (size_t)n * H + g * 4);
    atomicAdd(reinterpret_cast<float4*>(g_pool + (size_t)bg * H + g * 4), v);
    if (g == 0) atomicAdd(&g_cnt[bg], 1.0f);
}

// ---------------------------------------------------------------------------
// Final linear: out[G,2]
__global__ void k_final(const float* __restrict__ Wlin,
                        const float* __restrict__ blin,
                        float* __restrict__ out) {
    int g = blockIdx.x * blockDim.x + threadIdx.x;
    if (g >= N_GRAPHS) return;
    float invc = 1.0f / fmaxf(g_cnt[g], 1.0f);
    float a0 = blin[0], a1 = blin[1];
#pragma unroll
    for (int j = 0; j < H; j++) {
        float p = g_pool[(size_t)g * H + j] * invc;
        a0 += p * Wlin[j];
        a1 += p * Wlin[H + j];
    }
    out[g * 2 + 0] = a0;
    out[g * 2 + 1] = a1;
}

// ---------------------------------------------------------------------------
extern "C" void kernel_launch(void* const* d_in, const int* in_sizes, int n_in,
                              void* d_out, int out_size) {
    const float* x     = (const float*)d_in[0];
    const void*  ei    = d_in[1];
    const void*  batch = d_in[2];
    const float* W1_l  = (const float*)d_in[3];
    const float* b1    = (const float*)d_in[4];
    const float* W1_r  = (const float*)d_in[5];
    const float* W2_l  = (const float*)d_in[6];
    const float* b2    = (const float*)d_in[7];
    const float* W2_r  = (const float*)d_in[8];
    const float* W_lin = (const float*)d_in[9];
    const float* b_lin = (const float*)d_in[10];
    float* out = (float*)d_out;

    int E = in_sizes[1] / 2;

    k_probe<<<1, 32>>>(ei, in_sizes[1]);
    k_zero<<<1024, 256>>>();
    {
        long long t = (long long)E * 8;
        k_edge1<<<(unsigned)((t + 255) / 256), 256>>>(x, ei, E);
    }
    k_node1<<<(N_NODES + 255) / 256, 256>>>(x, W1_l, b1, W1_r);
    {
        long long t = (long long)E * 16;
        k_edge2<<<(unsigned)((t + 255) / 256), 256>>>(ei, E);
    }
    k_node2<<<(N_NODES + 127) / 128, 128>>>(W2_l, b2, W2_r);
    k_pool<<<(N_NODES * 16 + 255) / 256, 256>>>(batch);
    k_final<<<(N_GRAPHS + 127) / 128, 128>>>(W_lin, b_lin, out);
}